// round 1
// baseline (speedup 1.0000x reference)
#include <cuda_runtime.h>

#define B_   4
#define N_   4096
#define DIN  128
#define DH   64
#define DO   128
#define TM   128
#define TN   128
#define SP_STRIDE (TN + 4)
#define NEG_BIG (-9.0e15f)
#define NW   (N_/32)

// ---------------- scratch (static device allocations are allowed) ----------------
__device__ float    g_Whs[B_*N_*DH];      // 4 MB
__device__ float    g_Wht[B_*N_*DH];      // 4 MB
__device__ float    g_Whc[B_*N_*DO];      // 8 MB
__device__ unsigned g_adjbits[N_*NW];     // 2 MB

// ---------------- packed fp32 FMA (Blackwell f32x2, 2x FFMA throughput) ----------
__device__ __forceinline__ float2 ffma2(float2 a, float2 b, float2 c) {
    unsigned long long ua = *reinterpret_cast<unsigned long long*>(&a);
    unsigned long long ub = *reinterpret_cast<unsigned long long*>(&b);
    unsigned long long uc = *reinterpret_cast<unsigned long long*>(&c);
    unsigned long long ud;
    asm("fma.rn.f32x2 %0, %1, %2, %3;" : "=l"(ud) : "l"(ua), "l"(ub), "l"(uc));
    return *reinterpret_cast<float2*>(&ud);
}

// ---------------- kernel 1: projections h@Ws, h@Wt, h@Wc -------------------------
// block = 256 threads, 16 rows of h per block. shT is [k][r] so we can use packed
// row-pair accumulation.
__global__ void gat_proj_kernel(const float* __restrict__ h,
                                const float* __restrict__ Ws,
                                const float* __restrict__ Wt,
                                const float* __restrict__ Wc) {
    __shared__ float shT[DIN*16];     // transposed: [k][r]
    const int r0 = blockIdx.x * 16;

    for (int idx = threadIdx.x; idx < 16*(DIN/4); idx += 256) {
        int k4 = idx >> 4;
        int r  = idx & 15;
        float4 v = *(const float4*)(h + (size_t)(r0 + r)*DIN + k4*4);
        shT[(k4*4+0)*16 + r] = v.x;
        shT[(k4*4+1)*16 + r] = v.y;
        shT[(k4*4+2)*16 + r] = v.z;
        shT[(k4*4+3)*16 + r] = v.w;
    }
    __syncthreads();

    const int t = threadIdx.x;
    const float* Wp; int stride, c, ostride; float* outp;
    if (t < 64)       { Wp = Ws; stride = DH; c = t;       outp = g_Whs; ostride = DH; }
    else if (t < 128) { Wp = Wt; stride = DH; c = t - 64;  outp = g_Wht; ostride = DH; }
    else              { Wp = Wc; stride = DO; c = t - 128; outp = g_Whc; ostride = DO; }

    float2 acc[8];
#pragma unroll
    for (int q = 0; q < 8; q++) acc[q] = make_float2(0.f, 0.f);

#pragma unroll 4
    for (int k = 0; k < DIN; k++) {
        float  w  = Wp[k*stride + c];
        float2 wp = make_float2(w, w);
        const float2* hp = (const float2*)(shT + k*16);
#pragma unroll
        for (int q = 0; q < 8; q++) acc[q] = ffma2(wp, hp[q], acc[q]);
    }
#pragma unroll
    for (int q = 0; q < 8; q++) {
        outp[(size_t)(r0 + 2*q    )*ostride + c] = acc[q].x;
        outp[(size_t)(r0 + 2*q + 1)*ostride + c] = acc[q].y;
    }
}

// ---------------- kernel 2: pack adjacency into bitmask --------------------------
__global__ void gat_pack_adj_kernel(const int* __restrict__ adj) {
    const int row  = blockIdx.x;
    const int wi   = threadIdx.x >> 5;
    const int lane = threadIdx.x & 31;
#pragma unroll 4
    for (int w = 0; w < 32; w++) {
        int word = wi*32 + w;
        int col  = word*32 + lane;
        unsigned bit = (adj[(size_t)row*N_ + col] > 0) ? 1u : 0u;
        unsigned m = __ballot_sync(0xffffffffu, bit);
        if (lane == 0) g_adjbits[row*NW + word] = m;
    }
}

// ---------------- kernel 3: fused masked-softmax attention (flash style) ---------
// grid (N/TM, B), 256 threads = 16x16, 8x8 micro-tiles, packed f32x2 FMAs.
__global__ void __launch_bounds__(256, 1)
gat_attn_kernel(float* __restrict__ out) {
    extern __shared__ float smem[];
    float* sQ  = smem;                 // TM x DH   (row-major)
    float* sKT = sQ  + TM*DH;          // DH x TN   (k-major, keys contiguous)
    float* sV  = sKT + DH*TN;          // TN x DO   (row-major)
    float* sP  = sV  + TN*DO;          // TM x SP_STRIDE

    const int b    = blockIdx.y;
    const int row0 = blockIdx.x * TM;
    const int tid  = threadIdx.x;
    const int tx   = tid & 15;
    const int ty   = tid >> 4;
    const int ty8  = ty * 8;
    const int tx8  = tx * 8;

    const float* Whs = g_Whs + (size_t)b*N_*DH;
    const float* Wht = g_Wht + (size_t)b*N_*DH;
    const float* Whc = g_Whc + (size_t)b*N_*DO;

    // Q tile (contiguous copy)
    {
        const float4* src = (const float4*)(Whs + (size_t)row0*DH);
        float4* dst = (float4*)sQ;
        for (int idx = tid; idx < TM*DH/4; idx += 256) dst[idx] = src[idx];
    }

    float2 o2[8][4];
#pragma unroll
    for (int i = 0; i < 8; i++)
#pragma unroll
        for (int jp = 0; jp < 4; jp++) o2[i][jp] = make_float2(0.f, 0.f);
    float mrow[8], lrow[8];
#pragma unroll
    for (int i = 0; i < 8; i++) { mrow[i] = -3.0e38f; lrow[i] = 0.f; }

    for (int kt = 0; kt < N_/TN; kt++) {
        const int key0 = kt * TN;
        __syncthreads();   // protect smem from previous iteration's readers

        // load K tile transposed: sKT[k][key]
        for (int idx = tid; idx < TN*(DH/4); idx += 256) {
            int k4  = idx >> 7;          // 0..15
            int key = idx & (TN - 1);    // 0..127
            float4 v = *(const float4*)(Wht + (size_t)(key0 + key)*DH + k4*4);
            sKT[(k4*4+0)*TN + key] = v.x;
            sKT[(k4*4+1)*TN + key] = v.y;
            sKT[(k4*4+2)*TN + key] = v.z;
            sKT[(k4*4+3)*TN + key] = v.w;
        }
        // load V tile (contiguous)
        {
            const float4* src = (const float4*)(Whc + (size_t)key0*DO);
            float4* dst = (float4*)sV;
            for (int idx = tid; idx < TN*DO/4; idx += 256) dst[idx] = src[idx];
        }
        __syncthreads();

        // ---- S = Q @ K^T (128x128 tile, fp32, packed) ----
        float2 s2[8][4];
#pragma unroll
        for (int i = 0; i < 8; i++)
#pragma unroll
            for (int jp = 0; jp < 4; jp++) s2[i][jp] = make_float2(0.f, 0.f);

#pragma unroll 4
        for (int k4 = 0; k4 < DH/4; k4++) {
            float4 a4[8];
#pragma unroll
            for (int i = 0; i < 8; i++)
                a4[i] = *(const float4*)(sQ + (ty8 + i)*DH + k4*4);
#pragma unroll
            for (int kk = 0; kk < 4; kk++) {
                const float* bp = sKT + (k4*4 + kk)*TN + tx8;
                float4 b0 = *(const float4*)bp;
                float4 b1 = *(const float4*)(bp + 4);
                float2 bb[4];
                bb[0] = make_float2(b0.x, b0.y); bb[1] = make_float2(b0.z, b0.w);
                bb[2] = make_float2(b1.x, b1.y); bb[3] = make_float2(b1.z, b1.w);
#pragma unroll
                for (int i = 0; i < 8; i++) {
                    float av = (kk == 0) ? a4[i].x : (kk == 1) ? a4[i].y
                             : (kk == 2) ? a4[i].z : a4[i].w;
                    float2 ap = make_float2(av, av);
#pragma unroll
                    for (int jp = 0; jp < 4; jp++)
                        s2[i][jp] = ffma2(ap, bb[jp], s2[i][jp]);
                }
            }
        }

        // ---- mask + online softmax update ----
#pragma unroll
        for (int i = 0; i < 8; i++) {
            const int grow = row0 + ty8 + i;
            unsigned wbits = g_adjbits[grow*NW + (key0 >> 5) + (tx >> 2)];
            unsigned bits8 = wbits >> ((tx & 3) * 8);
#pragma unroll
            for (int jp = 0; jp < 4; jp++) {
                if (!((bits8 >> (2*jp    )) & 1u)) s2[i][jp].x = NEG_BIG;
                if (!((bits8 >> (2*jp + 1)) & 1u)) s2[i][jp].y = NEG_BIG;
            }
            float tm = fmaxf(fmaxf(fmaxf(s2[i][0].x, s2[i][0].y),
                                   fmaxf(s2[i][1].x, s2[i][1].y)),
                             fmaxf(fmaxf(s2[i][2].x, s2[i][2].y),
                                   fmaxf(s2[i][3].x, s2[i][3].y)));
#pragma unroll
            for (int off = 1; off < 16; off <<= 1)
                tm = fmaxf(tm, __shfl_xor_sync(0xffffffffu, tm, off));
            float mold  = mrow[i];
            float mnew  = fmaxf(mold, tm);
            float scale = __expf(mold - mnew);
            mrow[i] = mnew;
            float rs = 0.f;
#pragma unroll
            for (int jp = 0; jp < 4; jp++) {
                float px = __expf(s2[i][jp].x - mnew);
                float py = __expf(s2[i][jp].y - mnew);
                s2[i][jp].x = px; s2[i][jp].y = py;
                rs += px + py;
            }
#pragma unroll
            for (int off = 1; off < 16; off <<= 1)
                rs += __shfl_xor_sync(0xffffffffu, rs, off);
            lrow[i] = lrow[i]*scale + rs;
#pragma unroll
            for (int jp = 0; jp < 4; jp++) { o2[i][jp].x *= scale; o2[i][jp].y *= scale; }

            float4 p0 = make_float4(s2[i][0].x, s2[i][0].y, s2[i][1].x, s2[i][1].y);
            float4 p1 = make_float4(s2[i][2].x, s2[i][2].y, s2[i][3].x, s2[i][3].y);
            *(float4*)(sP + (ty8 + i)*SP_STRIDE + tx8    ) = p0;
            *(float4*)(sP + (ty8 + i)*SP_STRIDE + tx8 + 4) = p1;
        }
        __syncthreads();

        // ---- O += P @ V (128 keys x 128 out cols) ----
#pragma unroll 2
        for (int k4 = 0; k4 < TN/4; k4++) {
            float4 a4[8];
#pragma unroll
            for (int i = 0; i < 8; i++)
                a4[i] = *(const float4*)(sP + (ty8 + i)*SP_STRIDE + k4*4);
#pragma unroll
            for (int kk = 0; kk < 4; kk++) {
                const float* bp = sV + (k4*4 + kk)*DO + tx8;
                float4 b0 = *(const float4*)bp;
                float4 b1 = *(const float4*)(bp + 4);
                float2 bb[4];
                bb[0] = make_float2(b0.x, b0.y); bb[1] = make_float2(b0.z, b0.w);
                bb[2] = make_float2(b1.x, b1.y); bb[3] = make_float2(b1.z, b1.w);
#pragma unroll
                for (int i = 0; i < 8; i++) {
                    float av = (kk == 0) ? a4[i].x : (kk == 1) ? a4[i].y
                             : (kk == 2) ? a4[i].z : a4[i].w;
                    float2 ap = make_float2(av, av);
#pragma unroll
                    for (int jp = 0; jp < 4; jp++)
                        o2[i][jp] = ffma2(ap, bb[jp], o2[i][jp]);
                }
            }
        }
    }

    // ---- epilogue: normalize and store ----
#pragma unroll
    for (int i = 0; i < 8; i++) {
        float inv = 1.f / lrow[i];
        const int grow = row0 + ty8 + i;
        float4 r0v = make_float4(o2[i][0].x*inv, o2[i][0].y*inv,
                                 o2[i][1].x*inv, o2[i][1].y*inv);
        float4 r1v = make_float4(o2[i][2].x*inv, o2[i][2].y*inv,
                                 o2[i][3].x*inv, o2[i][3].y*inv);
        float4* op = (float4*)(out + ((size_t)b*N_ + grow)*DO + tx8);
        op[0] = r0v;
        op[1] = r1v;
    }
}

// ---------------- launch ----------------------------------------------------------
extern "C" void kernel_launch(void* const* d_in, const int* in_sizes, int n_in,
                              void* d_out, int out_size) {
    const float* h   = (const float*)d_in[0];
    const int*   adj = (const int*)  d_in[1];
    const float* Ws  = (const float*)d_in[2];
    const float* Wt  = (const float*)d_in[3];
    const float* Wc  = (const float*)d_in[4];
    float* out = (float*)d_out;

    const int smem_bytes = (TM*DH + DH*TN + TN*DO + TM*SP_STRIDE) * sizeof(float);
    cudaFuncSetAttribute(gat_attn_kernel,
                         cudaFuncAttributeMaxDynamicSharedMemorySize, smem_bytes);

    gat_proj_kernel<<<B_*N_/16, 256>>>(h, Ws, Wt, Wc);
    gat_pack_adj_kernel<<<N_, 128>>>(adj);
    gat_attn_kernel<<<dim3(N_/TM, B_), 256, smem_bytes>>>(out);
}